// round 5
// baseline (speedup 1.0000x reference)
#include <cuda_runtime.h>
#include <cstdint>

// Problem constants (from reference)
#define N_ATOMS   100000
#define N_PAIRS   6400000
#define NS        119
#define R_MAX     6.0f
#define PI_F      3.14159265358979323846f
#define LOG2E_F   1.4426950408889634f

#define THREADS   256
#define NBLK      ((N_PAIRS + THREADS - 1) / THREADS)   // 25000

// -------- device scratch (no allocations allowed) --------
__device__ float4 g_RZ[N_ATOMS];              // {x, y, z, as_float(Z)}
__device__ float4 g_tab[NS * NS * 4];         // 64B per (Zi,Zj) entry
__device__ float  g_partial[NBLK];

// Fast exp2/log2 via PTX (the __exp2f spelling is not a CUDA intrinsic).
// ex2/lg2.approx are exactly what __expf/__logf lower to, ~2^-21 rel err.
__device__ __forceinline__ float fex2(float x) {
    float y; asm("ex2.approx.ftz.f32 %0, %1;" : "=f"(y) : "f"(x)); return y;
}
__device__ __forceinline__ float flg2(float x) {
    float y; asm("lg2.approx.ftz.f32 %0, %1;" : "=f"(y) : "f"(x)); return y;
}

// softplus, matches jax.nn.softplus numerics: relu(x) + log1p(exp(-|x|))
__device__ __forceinline__ float sp(float x) {
    return fmaxf(x, 0.0f) + log1pf(expf(-fabsf(x)));
}

// -------- kernel 1: build packed pair-parameter table --------
// entry layout (floats): [pc0 pc1 pc2 pe0][pe1 pe2 De p1][p2 rinv0 0 0][pad]
__global__ void build_tab_kernel(const float* __restrict__ r0,
                                 const float* __restrict__ po_coeff,
                                 const float* __restrict__ po_exp,
                                 const float* __restrict__ De,
                                 const float* __restrict__ pbe1,
                                 const float* __restrict__ pbe2) {
    int e = blockIdx.x * blockDim.x + threadIdx.x;
    if (e >= NS * NS) return;
    int zi = e / NS;
    int zj = e - zi * NS;

    float4 q0, q1, q2;
    q0.x = sp(po_coeff[e * 3 + 0]);
    q0.y = sp(po_coeff[e * 3 + 1]);
    q0.z = sp(po_coeff[e * 3 + 2]);
    q0.w = sp(po_exp[e * 3 + 0]);
    q1.x = sp(po_exp[e * 3 + 1]);
    q1.y = sp(po_exp[e * 3 + 2]);
    q1.z = sp(De[e]);
    q1.w = pbe1[e];
    q2.x = sp(pbe2[e] + 1.0f);
    float r0ij = 0.5f * (sp(r0[zi]) + sp(r0[zj]));
    q2.y = 1.0f / r0ij;
    q2.z = 0.0f; q2.w = 0.0f;

    g_tab[e * 4 + 0] = q0;
    g_tab[e * 4 + 1] = q1;
    g_tab[e * 4 + 2] = q2;
}

// -------- kernel 2: pack positions + species into float4 --------
__global__ void pack_rz_kernel(const float* __restrict__ R,
                               const int* __restrict__ Z) {
    int i = blockIdx.x * blockDim.x + threadIdx.x;
    if (i >= N_ATOMS) return;
    g_RZ[i] = make_float4(R[3 * i + 0], R[3 * i + 1], R[3 * i + 2],
                          __int_as_float(Z[i]));
}

// -------- warp/block reduction helper --------
__device__ __forceinline__ float warp_sum(float v) {
    #pragma unroll
    for (int o = 16; o > 0; o >>= 1)
        v += __shfl_down_sync(0xffffffffu, v, o);
    return v;
}

// -------- kernel 3: main pair kernel --------
__global__ void __launch_bounds__(THREADS)
pair_kernel(const int* __restrict__ idx) {
    int p = blockIdx.x * blockDim.x + threadIdx.x;
    float E = 0.0f;

    if (p < N_PAIRS) {
        int i = idx[p];
        int j = idx[N_PAIRS + p];
        if (i != j) {
            float4 a = g_RZ[i];
            float4 b = g_RZ[j];
            float dx = b.x - a.x;
            float dy = b.y - a.y;
            float dz = b.z - a.z;
            float d2 = fmaf(dx, dx, fmaf(dy, dy, dz * dz));
            float dr = (d2 > 0.0f) ? sqrtf(d2) : 0.0f;
            float drc = fminf(dr, R_MAX);
            float cut = 0.5f * (__cosf(drc * (PI_F / R_MAX)) + 1.0f);

            int Zi = __float_as_int(a.w);
            int Zj = __float_as_int(b.w);
            const float4* t = &g_tab[(Zi * NS + Zj) * 4];
            float4 q0 = t[0];
            float4 q1 = t[1];
            float2 q2 = *reinterpret_cast<const float2*>(t + 2);

            float p2v  = q2.x;
            float rinv = q2.y;
            float ratio = dr * rinv;

            // ratio^pe_k = exp2(pe_k * log2(ratio)); share log2 across k
            float L = flg2(ratio);              // valid iff dr > 0
            float t0 = fex2(q0.w * L);
            float t1 = fex2(q1.x * L);
            float t2 = fex2(q1.y * L);
            if (!(dr > 0.0f)) { t0 = 0.0f; t1 = 0.0f; t2 = 0.0f; }  // safe_pow limit

            // exp(-pc_k * t_k) = exp2(-log2e * pc_k * t_k)
            float e0 = fex2(-LOG2E_F * q0.x * t0);
            float e1 = fex2(-LOG2E_F * q0.y * t1);
            float e2 = fex2(-LOG2E_F * q0.z * t2);
            float bo = cut * (e0 + e1 + e2);

            // bo^p2 (safe_pow: 0 at bo==0)
            float bp = (bo > 0.0f) ? fex2(p2v * flg2(bo)) : 0.0f;
            float De_ij = q1.z;
            float p1v   = q1.w;
            // exp(p1 * (1 - bp))
            float ef = fex2(LOG2E_F * p1v * (1.0f - bp));
            E = -De_ij * bo * ef;
        }
    }

    // block reduction to partials (deterministic)
    __shared__ float sh[THREADS / 32];
    float v = warp_sum(E);
    int lane = threadIdx.x & 31;
    int wid  = threadIdx.x >> 5;
    if (lane == 0) sh[wid] = v;
    __syncthreads();
    if (wid == 0) {
        v = (lane < (THREADS / 32)) ? sh[lane] : 0.0f;
        v = warp_sum(v);
        if (lane == 0) g_partial[blockIdx.x] = v;
    }
}

// -------- kernel 4: final deterministic reduction --------
__global__ void __launch_bounds__(1024)
reduce_kernel(float* __restrict__ out) {
    float s = 0.0f;
    for (int i = threadIdx.x; i < NBLK; i += 1024)
        s += g_partial[i];
    __shared__ float sh[32];
    float v = warp_sum(s);
    int lane = threadIdx.x & 31;
    int wid  = threadIdx.x >> 5;
    if (lane == 0) sh[wid] = v;
    __syncthreads();
    if (wid == 0) {
        v = (lane < 32) ? sh[lane] : 0.0f;
        v = warp_sum(v);
        if (lane == 0) out[0] = v;
    }
}

extern "C" void kernel_launch(void* const* d_in, const int* in_sizes, int n_in,
                              void* d_out, int out_size) {
    const float* R        = (const float*)d_in[0];
    const int*   Z        = (const int*)  d_in[1];
    const int*   idx      = (const int*)  d_in[2];
    const float* r0       = (const float*)d_in[3];
    const float* po_coeff = (const float*)d_in[4];
    const float* po_exp   = (const float*)d_in[5];
    const float* De       = (const float*)d_in[6];
    const float* pbe1     = (const float*)d_in[7];
    const float* pbe2     = (const float*)d_in[8];
    float* out = (float*)d_out;

    build_tab_kernel<<<(NS * NS + 255) / 256, 256>>>(r0, po_coeff, po_exp, De, pbe1, pbe2);
    pack_rz_kernel<<<(N_ATOMS + 255) / 256, 256>>>(R, Z);
    pair_kernel<<<NBLK, THREADS>>>(idx);
    reduce_kernel<<<1, 1024>>>(out);
}